// round 15
// baseline (speedup 1.0000x reference)
#include <cuda_runtime.h>
#include <cuda_fp16.h>
#include <math.h>
#include <stdint.h>

// Problem dims
#define BB   8
#define TT   128
#define NN   64
#define KH   8
#define DH   64
#define DD   512
#define MTOT 65536

// Scratch (device globals — allocation-free rule)
__device__ __align__(16) __half g_h[(size_t)MTOT*1536];    // fp16 concat(X,STE)
__device__ __align__(16) __half g_w[(size_t)3*512*1536];   // fp16 Wq|Wk|Wv
__device__ __align__(16) __half g_wo[(size_t)512*512];     // fp16 Wo
__device__ __align__(16) __half g_q[(size_t)BB*NN*KH*TT*DH];  // [B,N,K,T,d]
__device__ __align__(16) __half g_k[(size_t)BB*NN*KH*TT*DH];
__device__ __align__(16) __half g_v[(size_t)BB*NN*KH*TT*DH];
__device__ __align__(16) __half g_attn[(size_t)MTOT*DD];   // [B,T,N,D]

// ---------------------------------------------------------------------------
// Helpers
// ---------------------------------------------------------------------------
__device__ __forceinline__ uint32_t smem_u32(const void* p) {
    uint32_t a;
    asm("{ .reg .u64 t; cvta.to.shared.u64 t, %1; cvt.u32.u64 %0, t; }" : "=r"(a) : "l"(p));
    return a;
}

#define CP_ASYNC16(dst, src) \
    asm volatile("cp.async.cg.shared.global [%0], [%1], 16;" :: "r"(dst), "l"(src))
#define CP_COMMIT()  asm volatile("cp.async.commit_group;" ::: "memory")
#define CP_WAIT1()   asm volatile("cp.async.wait_group 1;" ::: "memory")
#define CP_WAIT0()   asm volatile("cp.async.wait_group 0;" ::: "memory")

#define LDMATRIX_X4(r0, r1, r2, r3, addr) \
    asm volatile("ldmatrix.sync.aligned.m8n8.x4.shared.b16 {%0,%1,%2,%3}, [%4];" \
                 : "=r"(r0), "=r"(r1), "=r"(r2), "=r"(r3) : "r"(addr))

#define LDMATRIX_X4_T(r0, r1, r2, r3, addr) \
    asm volatile("ldmatrix.sync.aligned.m8n8.x4.trans.shared.b16 {%0,%1,%2,%3}, [%4];" \
                 : "=r"(r0), "=r"(r1), "=r"(r2), "=r"(r3) : "r"(addr))

#define MMA_F16(d, a, b0, b1) \
    asm volatile("mma.sync.aligned.m16n8k16.row.col.f32.f16.f16.f32 " \
                 "{%0,%1,%2,%3}, {%4,%5,%6,%7}, {%8,%9}, {%0,%1,%2,%3};" \
                 : "+f"((d)[0]), "+f"((d)[1]), "+f"((d)[2]), "+f"((d)[3]) \
                 : "r"((a)[0]), "r"((a)[1]), "r"((a)[2]), "r"((a)[3]), \
                   "r"(b0), "r"(b1))

// GEMM SMEM: 2 stages x (A 16KB + B 16KB) = 64KB, bias 2048 B, +1024 align slack
#define STAGE_BYTES 32768
#define OFF_BIAS    65536
#define SMEM_REQ    (65536 + 2048 + 1024)

// Attention SMEM: Q,K,V 16KB each (128 rows x 128B swizzled), P 32KB (256B rows)
#define AT_Q    0
#define AT_K    16384
#define AT_V    32768
#define AT_P    49152
#define AT_SMEM 81920

// ---------------------------------------------------------------------------
// Merged prepass: fp16 conversion of activations (blocks 0..65535) and
// weights (blocks 65536..67583). Streaming writes (__stwt) keep the 201 MB
// g_h stream out of L2 — it is consumed once, later, by the QKV GEMM.
// ---------------------------------------------------------------------------
__global__ __launch_bounds__(384) void prep_all(
    const float* __restrict__ X, const float* __restrict__ STE,
    const float* __restrict__ Wq, const float* __restrict__ Wk,
    const float* __restrict__ Wv, const float* __restrict__ Wo)
{
    const int blk = blockIdx.x;
    if (blk < MTOT) {
        const int row = blk;
        const int c   = threadIdx.x * 4;
        float4 v;
        if (c < 512) v = *(const float4*)(X + (size_t)row * 512 + c);
        else         v = *(const float4*)(STE + (size_t)row * 1024 + (c - 512));
        __half2 h0 = __floats2half2_rn(v.x, v.y);
        __half2 h1 = __floats2half2_rn(v.z, v.w);
        float2 pk = make_float2(__uint_as_float(*(uint32_t*)&h0),
                                __uint_as_float(*(uint32_t*)&h1));
        __stwt((float2*)(g_h + (size_t)row * 1536 + c), pk);
    } else if (blk < MTOT + 1536) {
        const int b = blk - MTOT;
        const int z = b >> 9, n = b & 511;
        const float* W = (z == 0) ? Wq : (z == 1) ? Wk : Wv;
        const int c = threadIdx.x * 4;
        float4 v = *(const float4*)(W + (size_t)n * 1536 + c);
        __half2* dst = (__half2*)(g_w + (size_t)b * 1536 + c);
        dst[0] = __floats2half2_rn(v.x, v.y);
        dst[1] = __floats2half2_rn(v.z, v.w);
    } else {
        const int n = blk - MTOT - 1536;
        if (threadIdx.x < 128) {
            const int c = threadIdx.x * 4;
            float4 v = *(const float4*)(Wo + (size_t)n * 512 + c);
            __half2* dst = (__half2*)(g_wo + (size_t)n * 512 + c);
            dst[0] = __floats2half2_rn(v.x, v.y);
            dst[1] = __floats2half2_rn(v.z, v.w);
        }
    }
}

// ---------------------------------------------------------------------------
// Shared GEMM body: fp16 mma.sync (m16n8k16), cp.async 2-stage,
// CTA 128x128x64, 4 warps (2Mx2N), warp tile 64x64.  [round-10 config]
// ---------------------------------------------------------------------------
template<bool QKV>
__device__ __forceinline__ void gemm_body(
    const float* __restrict__ bias0, const float* __restrict__ bias1,
    const float* __restrict__ bias2, float* __restrict__ dout)
{
    constexpr int KDIM = QKV ? 1536 : 512;
    constexpr int NC   = KDIM / 64;

    extern __shared__ char raw[];
    const uint32_t sb_raw = smem_u32(raw);
    const uint32_t sb0 = (sb_raw + 1023u) & ~1023u;
    char* sm = raw + (sb0 - sb_raw);
    float* s_bias = (float*)(sm + OFF_BIAS);

    const int tid  = threadIdx.x;
    const int lane = tid & 31;
    const int wid  = tid >> 5;
    const int wm   = wid & 1;
    const int wn   = wid >> 1;

    const int n0 = QKV ? (blockIdx.x & 3) * 128 : blockIdx.x * 128;
    const int z  = QKV ? (blockIdx.x >> 2) : 0;
    const int m0 = blockIdx.y * 128;

    const __half* __restrict__ A = QKV ? g_h : g_attn;
    const __half* __restrict__ W = QKV ? (g_w + (size_t)z * 512 * 1536) : g_wo;
    const float* __restrict__ bias = (z == 0) ? bias0 : (z == 1) ? bias1 : bias2;

    ((float4*)s_bias)[tid] = ((const float4*)bias)[tid];

    auto issue = [&](int kc, int stage) {
        const uint32_t as = sb0 + stage * STAGE_BYTES;
        const uint32_t bs = as + 16384;
        const __half* Ap = A + (size_t)m0 * KDIM + kc * 64;
        const __half* Wp = W + (size_t)n0 * KDIM + kc * 64;
        #pragma unroll
        for (int it = 0; it < 8; ++it) {
            const int pos = tid + it * 128;
            const int row = pos >> 3, c8 = pos & 7;
            const uint32_t d = as + row * 128 + ((c8 * 16) ^ ((row & 7) * 16));
            CP_ASYNC16(d, Ap + (size_t)row * KDIM + c8 * 8);
        }
        #pragma unroll
        for (int it = 0; it < 8; ++it) {
            const int pos = tid + it * 128;
            const int row = pos >> 3, c8 = pos & 7;
            const uint32_t d = bs + row * 128 + ((c8 * 16) ^ ((row & 7) * 16));
            CP_ASYNC16(d, Wp + (size_t)row * KDIM + c8 * 8);
        }
    };

    float acc[4][8][4];
    #pragma unroll
    for (int i = 0; i < 4; ++i)
        #pragma unroll
        for (int j = 0; j < 8; ++j)
            #pragma unroll
            for (int c = 0; c < 4; ++c) acc[i][j][c] = 0.f;

    const int a_row = wm * 64 + ((lane >> 3) & 1) * 8 + (lane & 7);
    const int a_kb  = (lane >> 4) * 16;
    const int xa    = (a_row & 7) * 16;
    const int b_row = wn * 64 + ((lane >> 3) & 1) * 8 + (lane & 7);
    const int b_kb  = (lane >> 4) * 16;
    const int xb    = (b_row & 7) * 16;

    auto compute = [&](int buf) {
        const uint32_t abase = sb0 + buf * STAGE_BYTES;
        const uint32_t bbase = abase + 16384;
        #pragma unroll
        for (int ks = 0; ks < 4; ++ks) {
            uint32_t af[4][4], bf[4][4];
            #pragma unroll
            for (int mt = 0; mt < 4; ++mt)
                LDMATRIX_X4(af[mt][0], af[mt][1], af[mt][2], af[mt][3],
                            abase + (a_row + mt * 16) * 128 + ((ks * 32 + a_kb) ^ xa));
            #pragma unroll
            for (int np = 0; np < 4; ++np)
                LDMATRIX_X4(bf[np][0], bf[np][1], bf[np][2], bf[np][3],
                            bbase + (b_row + np * 16) * 128 + ((ks * 32 + b_kb) ^ xb));
            #pragma unroll
            for (int mt = 0; mt < 4; ++mt)
                #pragma unroll
                for (int np = 0; np < 4; ++np) {
                    MMA_F16(acc[mt][2*np],   af[mt], bf[np][0], bf[np][2]);
                    MMA_F16(acc[mt][2*np+1], af[mt], bf[np][1], bf[np][3]);
                }
        }
    };

    issue(0, 0); CP_COMMIT();
    issue(1, 1); CP_COMMIT();

    #pragma unroll 1
    for (int c = 0; c < NC; ++c) {
        if (c + 1 < NC) { CP_WAIT1(); } else { CP_WAIT0(); }
        __syncthreads();                 // publish chunk c
        compute(c & 1);
        __syncthreads();                 // all warps done reading stage c&1
        if (c + 2 < NC) { issue(c + 2, c & 1); CP_COMMIT(); }
    }

    __half* gq = g_q; __half* gk = g_k; __half* gv = g_v;
    #pragma unroll
    for (int mt = 0; mt < 4; ++mt) {
        const int R0 = m0 + wm * 64 + mt * 16 + (lane >> 2);
        const int R1 = R0 + 8;
        #pragma unroll
        for (int nt = 0; nt < 8; ++nt) {
            const int o = n0 + wn * 64 + nt * 8 + (lane & 3) * 2;
            const float bx = s_bias[o], by = s_bias[o + 1];
            float v0 = acc[mt][nt][0] + bx; v0 = v0 > 0.f ? v0 : 0.f;
            float v1 = acc[mt][nt][1] + by; v1 = v1 > 0.f ? v1 : 0.f;
            float v2 = acc[mt][nt][2] + bx; v2 = v2 > 0.f ? v2 : 0.f;
            float v3 = acc[mt][nt][3] + by; v3 = v3 > 0.f ? v3 : 0.f;
            if (QKV) {
                __half* outp = (z == 0) ? gq : (z == 1) ? gk : gv;
                const int head = o >> 6, jj = o & 63;
                {
                    const int b_ = R0 >> 13, t_ = (R0 >> 6) & 127, n_ = R0 & 63;
                    const size_t idx = (((size_t)(b_ * NN + n_) * KH + head) * TT + t_) * DH + jj;
                    *(__half2*)(outp + idx) = __floats2half2_rn(v0, v1);
                }
                {
                    const int b_ = R1 >> 13, t_ = (R1 >> 6) & 127, n_ = R1 & 63;
                    const size_t idx = (((size_t)(b_ * NN + n_) * KH + head) * TT + t_) * DH + jj;
                    *(__half2*)(outp + idx) = __floats2half2_rn(v2, v3);
                }
            } else {
                *(float2*)(dout + (size_t)R0 * DD + o) = make_float2(v0, v1);
                *(float2*)(dout + (size_t)R1 * DD + o) = make_float2(v2, v3);
            }
        }
    }
}

// QKV: (128,3) — measured best despite reg cap (rounds 9 vs 10)
__global__ __launch_bounds__(128, 3) void gemm_qkv(
    const float* __restrict__ b0, const float* __restrict__ b1,
    const float* __restrict__ b2)
{
    gemm_body<true>(b0, b1, b2, nullptr);
}

// Proj: (128,2) — lift the register cap so the mainloop doesn't spill
__global__ __launch_bounds__(128, 2) void gemm_proj(
    const float* __restrict__ b, float* __restrict__ dout)
{
    gemm_body<false>(b, b, b, dout);
}

// ---------------------------------------------------------------------------
// fp16 tensor-core attention (round-10 version, ~80 us): one CTA per
// (b,n,head), 256 thr = 8 warps. V consumed via ldmatrix.trans.
// ---------------------------------------------------------------------------
__global__ __launch_bounds__(256, 2) void attn_tc()
{
    extern __shared__ char smf[];
    const uint32_t sb = smem_u32(smf);

    const int head = blockIdx.x;
    const int n    = blockIdx.y;
    const int b    = blockIdx.z;
    const size_t base = ((size_t)(b * NN + n) * KH + head) * (TT * DH);

    const int tid  = threadIdx.x;
    const int lane = tid & 31;
    const int w    = tid >> 5;

    {
        const __half* qg = g_q + base;
        const __half* kg = g_k + base;
        const __half* vg = g_v + base;
        #pragma unroll
        for (int it = 0; it < 4; ++it) {
            const int pos = tid + it * 256;
            const int r = pos >> 3, c8 = pos & 7;
            const uint32_t off = r * 128 + ((c8 * 16) ^ ((r & 7) * 16));
            CP_ASYNC16(sb + AT_Q + off, qg + (size_t)pos * 8);
            CP_ASYNC16(sb + AT_K + off, kg + (size_t)pos * 8);
            CP_ASYNC16(sb + AT_V + off, vg + (size_t)pos * 8);
        }
        CP_COMMIT();
        CP_WAIT0();
    }
    __syncthreads();

    const int arow = w * 16 + ((lane >> 3) & 1) * 8 + (lane & 7);
    const int akb  = (lane >> 4) * 16;
    const int xa   = (arow & 7) * 16;
    const int brow8 = ((lane >> 3) & 1) * 8 + (lane & 7);
    const int bkb   = (lane >> 4) * 16;

    float acc[16][4];
    #pragma unroll
    for (int i = 0; i < 16; ++i)
        #pragma unroll
        for (int c = 0; c < 4; ++c) acc[i][c] = 0.f;

    #pragma unroll
    for (int ks = 0; ks < 4; ++ks) {
        uint32_t af[4];
        LDMATRIX_X4(af[0], af[1], af[2], af[3],
                    sb + AT_Q + arow * 128 + ((ks * 32 + akb) ^ xa));
        #pragma unroll
        for (int np = 0; np < 8; ++np) {
            const int srow = np * 16 + brow8;
            uint32_t bf[4];
            LDMATRIX_X4(bf[0], bf[1], bf[2], bf[3],
                        sb + AT_K + srow * 128 + ((ks * 32 + bkb) ^ ((srow & 7) * 16)));
            MMA_F16(acc[2*np],   af, bf[0], bf[2]);
            MMA_F16(acc[2*np+1], af, bf[1], bf[3]);
        }
    }

    const int r0 = w * 16 + (lane >> 2);
    float mx0 = -1e30f, mx1 = -1e30f;
    #pragma unroll
    for (int nt = 0; nt < 16; ++nt) {
        const int c0 = nt * 8 + (lane & 3) * 2;
        acc[nt][0] = (c0     <= r0    ) ? acc[nt][0] * 0.125f : -1e30f;
        acc[nt][1] = (c0 + 1 <= r0    ) ? acc[nt][1] * 0.125f : -1e30f;
        acc[nt][2] = (c0     <= r0 + 8) ? acc[nt][2] * 0.125f : -1e30f;
        acc[nt][3] = (c0 + 1 <= r0 + 8) ? acc[nt][3] * 0.125f : -1e30f;
        mx0 = fmaxf(mx0, fmaxf(acc[nt][0], acc[nt][1]));
        mx1 = fmaxf(mx1, fmaxf(acc[nt][2], acc[nt][3]));
    }
    mx0 = fmaxf(mx0, __shfl_xor_sync(0xffffffffu, mx0, 1));
    mx0 = fmaxf(mx0, __shfl_xor_sync(0xffffffffu, mx0, 2));
    mx1 = fmaxf(mx1, __shfl_xor_sync(0xffffffffu, mx1, 1));
    mx1 = fmaxf(mx1, __shfl_xor_sync(0xffffffffu, mx1, 2));

    float l0 = 0.f, l1 = 0.f;
    #pragma unroll
    for (int nt = 0; nt < 16; ++nt) {
        acc[nt][0] = __expf(acc[nt][0] - mx0);
        acc[nt][1] = __expf(acc[nt][1] - mx0);
        acc[nt][2] = __expf(acc[nt][2] - mx1);
        acc[nt][3] = __expf(acc[nt][3] - mx1);
        l0 += acc[nt][0] + acc[nt][1];
        l1 += acc[nt][2] + acc[nt][3];
    }
    l0 += __shfl_xor_sync(0xffffffffu, l0, 1);
    l0 += __shfl_xor_sync(0xffffffffu, l0, 2);
    l1 += __shfl_xor_sync(0xffffffffu, l1, 1);
    l1 += __shfl_xor_sync(0xffffffffu, l1, 2);
    const float inv0 = 1.f / l0, inv1 = 1.f / l1;

    {
        const uint32_t p0 = sb + AT_P + r0 * 256;
        const uint32_t p1 = sb + AT_P + (r0 + 8) * 256;
        const int cb = (lane & 3) * 4;
        const int x0 = (r0 & 7) * 16, x1 = ((r0 + 8) & 7) * 16;
        #pragma unroll
        for (int nt = 0; nt < 16; ++nt) {
            __half2 h0 = __floats2half2_rn(acc[nt][0], acc[nt][1]);
            __half2 h1 = __floats2half2_rn(acc[nt][2], acc[nt][3]);
            *(__half2*)(smf + (p0 - sb) + ((nt * 16 + cb) ^ x0)) = h0;
            *(__half2*)(smf + (p1 - sb) + ((nt * 16 + cb) ^ x1)) = h1;
        }
    }
    __syncwarp();   // warp reads only its own P rows below

    float ao[8][4];
    #pragma unroll
    for (int i = 0; i < 8; ++i)
        #pragma unroll
        for (int c = 0; c < 4; ++c) ao[i][c] = 0.f;

    const int ks_max = w + 1;
    #pragma unroll 1
    for (int ks = 0; ks < ks_max; ++ks) {
        uint32_t af[4];
        LDMATRIX_X4(af[0], af[1], af[2], af[3],
                    sb + AT_P + arow * 256 + ((ks * 32 + akb) ^ xa));
        #pragma unroll
        for (int np = 0; np < 4; ++np) {
            const int srow = ks * 16 + brow8;
            uint32_t bf[4];
            LDMATRIX_X4_T(bf[0], bf[1], bf[2], bf[3],
                          sb + AT_V + srow * 128 + ((np * 32 + bkb) ^ ((srow & 7) * 16)));
            MMA_F16(ao[2*np],   af, bf[0], bf[1]);
            MMA_F16(ao[2*np+1], af, bf[2], bf[3]);
        }
    }

    {
        const size_t row0 = ((size_t)(b * TT + r0) * NN + n) * DD + head * DH
                          + (lane & 3) * 2;
        const size_t row1 = ((size_t)(b * TT + r0 + 8) * NN + n) * DD + head * DH
                          + (lane & 3) * 2;
        #pragma unroll
        for (int nt = 0; nt < 8; ++nt) {
            *(__half2*)(g_attn + row0 + nt * 8) =
                __floats2half2_rn(ao[nt][0] * inv0, ao[nt][1] * inv0);
            *(__half2*)(g_attn + row1 + nt * 8) =
                __floats2half2_rn(ao[nt][2] * inv1, ao[nt][3] * inv1);
        }
    }
}

// ---------------------------------------------------------------------------
extern "C" void kernel_launch(void* const* d_in, const int* in_sizes, int n_in,
                              void* d_out, int out_size)
{
    const float* X   = (const float*)d_in[0];
    const float* STE = (const float*)d_in[1];
    const float* Wq  = (const float*)d_in[2];
    const float* bq  = (const float*)d_in[3];
    const float* Wk  = (const float*)d_in[4];
    const float* bk  = (const float*)d_in[5];
    const float* Wv  = (const float*)d_in[6];
    const float* bv  = (const float*)d_in[7];
    const float* Wo  = (const float*)d_in[8];
    const float* bo  = (const float*)d_in[9];
    float* out = (float*)d_out;

    cudaFuncSetAttribute(gemm_qkv,  cudaFuncAttributeMaxDynamicSharedMemorySize, SMEM_REQ);
    cudaFuncSetAttribute(gemm_proj, cudaFuncAttributeMaxDynamicSharedMemorySize, SMEM_REQ);
    cudaFuncSetAttribute(attn_tc,   cudaFuncAttributeMaxDynamicSharedMemorySize, AT_SMEM);

    // Merged prepass: activations + all weights in one launch
    prep_all<<<MTOT + 1536 + 512, 384>>>(X, STE, Wq, Wk, Wv, Wo);

    // QKV: grid (z*4+ntile, mtile) — z-adjacent CTAs reuse the A m-tile in L2
    gemm_qkv<<<dim3(12, 512), 128, SMEM_REQ>>>(bq, bk, bv);
    attn_tc<<<dim3(KH, NN, BB), 256, AT_SMEM>>>();
    gemm_proj<<<dim3(4, 512), 128, SMEM_REQ>>>(bo, out);
}

// round 16
// speedup vs baseline: 1.0039x; 1.0039x over previous
#include <cuda_runtime.h>
#include <cuda_fp16.h>
#include <math.h>
#include <stdint.h>

// Problem dims
#define BB   8
#define TT   128
#define NN   64
#define KH   8
#define DH   64
#define DD   512
#define MTOT 65536

// Scratch (device globals — allocation-free rule)
__device__ __align__(16) __half g_h[(size_t)MTOT*1536];    // fp16 concat(X,STE)
__device__ __align__(16) __half g_w[(size_t)3*512*1536];   // fp16 Wq|Wk|Wv
__device__ __align__(16) __half g_wo[(size_t)512*512];     // fp16 Wo
__device__ __align__(16) __half g_q[(size_t)BB*NN*KH*TT*DH];  // [B,N,K,T,d]
__device__ __align__(16) __half g_k[(size_t)BB*NN*KH*TT*DH];
__device__ __align__(16) __half g_v[(size_t)BB*NN*KH*TT*DH];
__device__ __align__(16) __half g_attn[(size_t)MTOT*DD];   // [B,T,N,D]

// ---------------------------------------------------------------------------
// Helpers
// ---------------------------------------------------------------------------
__device__ __forceinline__ uint32_t smem_u32(const void* p) {
    uint32_t a;
    asm("{ .reg .u64 t; cvta.to.shared.u64 t, %1; cvt.u32.u64 %0, t; }" : "=r"(a) : "l"(p));
    return a;
}

#define CP_ASYNC16(dst, src) \
    asm volatile("cp.async.cg.shared.global [%0], [%1], 16;" :: "r"(dst), "l"(src))
#define CP_COMMIT()  asm volatile("cp.async.commit_group;" ::: "memory")
#define CP_WAIT1()   asm volatile("cp.async.wait_group 1;" ::: "memory")
#define CP_WAIT0()   asm volatile("cp.async.wait_group 0;" ::: "memory")

#define LDMATRIX_X4(r0, r1, r2, r3, addr) \
    asm volatile("ldmatrix.sync.aligned.m8n8.x4.shared.b16 {%0,%1,%2,%3}, [%4];" \
                 : "=r"(r0), "=r"(r1), "=r"(r2), "=r"(r3) : "r"(addr))

#define LDMATRIX_X4_T(r0, r1, r2, r3, addr) \
    asm volatile("ldmatrix.sync.aligned.m8n8.x4.trans.shared.b16 {%0,%1,%2,%3}, [%4];" \
                 : "=r"(r0), "=r"(r1), "=r"(r2), "=r"(r3) : "r"(addr))

#define MMA_F16(d, a, b0, b1) \
    asm volatile("mma.sync.aligned.m16n8k16.row.col.f32.f16.f16.f32 " \
                 "{%0,%1,%2,%3}, {%4,%5,%6,%7}, {%8,%9}, {%0,%1,%2,%3};" \
                 : "+f"((d)[0]), "+f"((d)[1]), "+f"((d)[2]), "+f"((d)[3]) \
                 : "r"((a)[0]), "r"((a)[1]), "r"((a)[2]), "r"((a)[3]), \
                   "r"(b0), "r"(b1))

// GEMM SMEM: 2 stages x (A 16KB + B 16KB) = 64KB, bias 2048 B, +1024 align slack
#define STAGE_BYTES 32768
#define OFF_BIAS    65536
#define SMEM_REQ    (65536 + 2048 + 1024)

// Attention SMEM: Q,K,V 16KB each (128 rows x 128B swizzled), P 32KB (256B rows)
#define AT_Q    0
#define AT_K    16384
#define AT_V    32768
#define AT_P    49152
#define AT_SMEM 81920

// ---------------------------------------------------------------------------
// Merged prepass: fp16 conversion of activations (blocks 0..65535) and
// weights (blocks 65536..67583). Streaming writes (__stwt) keep the 201 MB
// g_h stream out of L2 — it is consumed once, later, by the QKV GEMM.
// ---------------------------------------------------------------------------
__global__ __launch_bounds__(384) void prep_all(
    const float* __restrict__ X, const float* __restrict__ STE,
    const float* __restrict__ Wq, const float* __restrict__ Wk,
    const float* __restrict__ Wv, const float* __restrict__ Wo)
{
    const int blk = blockIdx.x;
    if (blk < MTOT) {
        const int row = blk;
        const int c   = threadIdx.x * 4;
        float4 v;
        if (c < 512) v = *(const float4*)(X + (size_t)row * 512 + c);
        else         v = *(const float4*)(STE + (size_t)row * 1024 + (c - 512));
        __half2 h0 = __floats2half2_rn(v.x, v.y);
        __half2 h1 = __floats2half2_rn(v.z, v.w);
        float2 pk = make_float2(__uint_as_float(*(uint32_t*)&h0),
                                __uint_as_float(*(uint32_t*)&h1));
        __stwt((float2*)(g_h + (size_t)row * 1536 + c), pk);
    } else if (blk < MTOT + 1536) {
        const int b = blk - MTOT;
        const int z = b >> 9, n = b & 511;
        const float* W = (z == 0) ? Wq : (z == 1) ? Wk : Wv;
        const int c = threadIdx.x * 4;
        float4 v = *(const float4*)(W + (size_t)n * 1536 + c);
        __half2* dst = (__half2*)(g_w + (size_t)b * 1536 + c);
        dst[0] = __floats2half2_rn(v.x, v.y);
        dst[1] = __floats2half2_rn(v.z, v.w);
    } else {
        const int n = blk - MTOT - 1536;
        if (threadIdx.x < 128) {
            const int c = threadIdx.x * 4;
            float4 v = *(const float4*)(Wo + (size_t)n * 512 + c);
            __half2* dst = (__half2*)(g_wo + (size_t)n * 512 + c);
            dst[0] = __floats2half2_rn(v.x, v.y);
            dst[1] = __floats2half2_rn(v.z, v.w);
        }
    }
}

// ---------------------------------------------------------------------------
// fp16 mma.sync GEMM (m16n8k16), cp.async 2-stage, 3 CTAs/SM (12 warps/SM).
// CTA 128x128x64, 4 warps (2Mx2N), warp tile 64x64.  [round-10/14 config —
// best measured of 7 variants; (128,3) beats no-spill (128,2) on occupancy]
// QKV=true : A=g_h (K=1536), W=g_w[z], fp16 scatter into g_q/g_k/g_v
// QKV=false: A=g_attn (K=512), W=g_wo, fp32 epilogue into dout
// ---------------------------------------------------------------------------
template<bool QKV>
__global__ __launch_bounds__(128, 3) void gemm3(
    const float* __restrict__ bias0, const float* __restrict__ bias1,
    const float* __restrict__ bias2, float* __restrict__ dout)
{
    constexpr int KDIM = QKV ? 1536 : 512;
    constexpr int NC   = KDIM / 64;

    extern __shared__ char raw[];
    const uint32_t sb_raw = smem_u32(raw);
    const uint32_t sb0 = (sb_raw + 1023u) & ~1023u;
    char* sm = raw + (sb0 - sb_raw);
    float* s_bias = (float*)(sm + OFF_BIAS);

    const int tid  = threadIdx.x;
    const int lane = tid & 31;
    const int wid  = tid >> 5;
    const int wm   = wid & 1;
    const int wn   = wid >> 1;

    const int n0 = QKV ? (blockIdx.x & 3) * 128 : blockIdx.x * 128;
    const int z  = QKV ? (blockIdx.x >> 2) : 0;
    const int m0 = blockIdx.y * 128;

    const __half* __restrict__ A = QKV ? g_h : g_attn;
    const __half* __restrict__ W = QKV ? (g_w + (size_t)z * 512 * 1536) : g_wo;
    const float* __restrict__ bias = (z == 0) ? bias0 : (z == 1) ? bias1 : bias2;

    ((float4*)s_bias)[tid] = ((const float4*)bias)[tid];

    auto issue = [&](int kc, int stage) {
        const uint32_t as = sb0 + stage * STAGE_BYTES;
        const uint32_t bs = as + 16384;
        const __half* Ap = A + (size_t)m0 * KDIM + kc * 64;
        const __half* Wp = W + (size_t)n0 * KDIM + kc * 64;
        #pragma unroll
        for (int it = 0; it < 8; ++it) {
            const int pos = tid + it * 128;
            const int row = pos >> 3, c8 = pos & 7;
            const uint32_t d = as + row * 128 + ((c8 * 16) ^ ((row & 7) * 16));
            CP_ASYNC16(d, Ap + (size_t)row * KDIM + c8 * 8);
        }
        #pragma unroll
        for (int it = 0; it < 8; ++it) {
            const int pos = tid + it * 128;
            const int row = pos >> 3, c8 = pos & 7;
            const uint32_t d = bs + row * 128 + ((c8 * 16) ^ ((row & 7) * 16));
            CP_ASYNC16(d, Wp + (size_t)row * KDIM + c8 * 8);
        }
    };

    float acc[4][8][4];
    #pragma unroll
    for (int i = 0; i < 4; ++i)
        #pragma unroll
        for (int j = 0; j < 8; ++j)
            #pragma unroll
            for (int c = 0; c < 4; ++c) acc[i][j][c] = 0.f;

    const int a_row = wm * 64 + ((lane >> 3) & 1) * 8 + (lane & 7);
    const int a_kb  = (lane >> 4) * 16;
    const int xa    = (a_row & 7) * 16;
    const int b_row = wn * 64 + ((lane >> 3) & 1) * 8 + (lane & 7);
    const int b_kb  = (lane >> 4) * 16;
    const int xb    = (b_row & 7) * 16;

    auto compute = [&](int buf) {
        const uint32_t abase = sb0 + buf * STAGE_BYTES;
        const uint32_t bbase = abase + 16384;
        #pragma unroll
        for (int ks = 0; ks < 4; ++ks) {
            uint32_t af[4][4], bf[4][4];
            #pragma unroll
            for (int mt = 0; mt < 4; ++mt)
                LDMATRIX_X4(af[mt][0], af[mt][1], af[mt][2], af[mt][3],
                            abase + (a_row + mt * 16) * 128 + ((ks * 32 + a_kb) ^ xa));
            #pragma unroll
            for (int np = 0; np < 4; ++np)
                LDMATRIX_X4(bf[np][0], bf[np][1], bf[np][2], bf[np][3],
                            bbase + (b_row + np * 16) * 128 + ((ks * 32 + b_kb) ^ xb));
            #pragma unroll
            for (int mt = 0; mt < 4; ++mt)
                #pragma unroll
                for (int np = 0; np < 4; ++np) {
                    MMA_F16(acc[mt][2*np],   af[mt], bf[np][0], bf[np][2]);
                    MMA_F16(acc[mt][2*np+1], af[mt], bf[np][1], bf[np][3]);
                }
        }
    };

    issue(0, 0); CP_COMMIT();
    issue(1, 1); CP_COMMIT();

    #pragma unroll 1
    for (int c = 0; c < NC; ++c) {
        if (c + 1 < NC) { CP_WAIT1(); } else { CP_WAIT0(); }
        __syncthreads();                 // publish chunk c
        compute(c & 1);
        __syncthreads();                 // all warps done reading stage c&1
        if (c + 2 < NC) { issue(c + 2, c & 1); CP_COMMIT(); }
    }

    __half* gq = g_q; __half* gk = g_k; __half* gv = g_v;
    #pragma unroll
    for (int mt = 0; mt < 4; ++mt) {
        const int R0 = m0 + wm * 64 + mt * 16 + (lane >> 2);
        const int R1 = R0 + 8;
        #pragma unroll
        for (int nt = 0; nt < 8; ++nt) {
            const int o = n0 + wn * 64 + nt * 8 + (lane & 3) * 2;
            const float bx = s_bias[o], by = s_bias[o + 1];
            float v0 = acc[mt][nt][0] + bx; v0 = v0 > 0.f ? v0 : 0.f;
            float v1 = acc[mt][nt][1] + by; v1 = v1 > 0.f ? v1 : 0.f;
            float v2 = acc[mt][nt][2] + bx; v2 = v2 > 0.f ? v2 : 0.f;
            float v3 = acc[mt][nt][3] + by; v3 = v3 > 0.f ? v3 : 0.f;
            if (QKV) {
                __half* outp = (z == 0) ? gq : (z == 1) ? gk : gv;
                const int head = o >> 6, jj = o & 63;
                {
                    const int b_ = R0 >> 13, t_ = (R0 >> 6) & 127, n_ = R0 & 63;
                    const size_t idx = (((size_t)(b_ * NN + n_) * KH + head) * TT + t_) * DH + jj;
                    *(__half2*)(outp + idx) = __floats2half2_rn(v0, v1);
                }
                {
                    const int b_ = R1 >> 13, t_ = (R1 >> 6) & 127, n_ = R1 & 63;
                    const size_t idx = (((size_t)(b_ * NN + n_) * KH + head) * TT + t_) * DH + jj;
                    *(__half2*)(outp + idx) = __floats2half2_rn(v2, v3);
                }
            } else {
                *(float2*)(dout + (size_t)R0 * DD + o) = make_float2(v0, v1);
                *(float2*)(dout + (size_t)R1 * DD + o) = make_float2(v2, v3);
            }
        }
    }
}

// ---------------------------------------------------------------------------
// fp16 tensor-core attention (round-10 version, ~80 us — near DRAM/regfile
// floor): one CTA per (b,n,head), 256 thr = 8 warps. V via ldmatrix.trans.
// ---------------------------------------------------------------------------
__global__ __launch_bounds__(256, 2) void attn_tc()
{
    extern __shared__ char smf[];
    const uint32_t sb = smem_u32(smf);

    const int head = blockIdx.x;
    const int n    = blockIdx.y;
    const int b    = blockIdx.z;
    const size_t base = ((size_t)(b * NN + n) * KH + head) * (TT * DH);

    const int tid  = threadIdx.x;
    const int lane = tid & 31;
    const int w    = tid >> 5;

    {
        const __half* qg = g_q + base;
        const __half* kg = g_k + base;
        const __half* vg = g_v + base;
        #pragma unroll
        for (int it = 0; it < 4; ++it) {
            const int pos = tid + it * 256;
            const int r = pos >> 3, c8 = pos & 7;
            const uint32_t off = r * 128 + ((c8 * 16) ^ ((r & 7) * 16));
            CP_ASYNC16(sb + AT_Q + off, qg + (size_t)pos * 8);
            CP_ASYNC16(sb + AT_K + off, kg + (size_t)pos * 8);
            CP_ASYNC16(sb + AT_V + off, vg + (size_t)pos * 8);
        }
        CP_COMMIT();
        CP_WAIT0();
    }
    __syncthreads();

    const int arow = w * 16 + ((lane >> 3) & 1) * 8 + (lane & 7);
    const int akb  = (lane >> 4) * 16;
    const int xa   = (arow & 7) * 16;
    const int brow8 = ((lane >> 3) & 1) * 8 + (lane & 7);
    const int bkb   = (lane >> 4) * 16;

    float acc[16][4];
    #pragma unroll
    for (int i = 0; i < 16; ++i)
        #pragma unroll
        for (int c = 0; c < 4; ++c) acc[i][c] = 0.f;

    #pragma unroll
    for (int ks = 0; ks < 4; ++ks) {
        uint32_t af[4];
        LDMATRIX_X4(af[0], af[1], af[2], af[3],
                    sb + AT_Q + arow * 128 + ((ks * 32 + akb) ^ xa));
        #pragma unroll
        for (int np = 0; np < 8; ++np) {
            const int srow = np * 16 + brow8;
            uint32_t bf[4];
            LDMATRIX_X4(bf[0], bf[1], bf[2], bf[3],
                        sb + AT_K + srow * 128 + ((ks * 32 + bkb) ^ ((srow & 7) * 16)));
            MMA_F16(acc[2*np],   af, bf[0], bf[2]);
            MMA_F16(acc[2*np+1], af, bf[1], bf[3]);
        }
    }

    const int r0 = w * 16 + (lane >> 2);
    float mx0 = -1e30f, mx1 = -1e30f;
    #pragma unroll
    for (int nt = 0; nt < 16; ++nt) {
        const int c0 = nt * 8 + (lane & 3) * 2;
        acc[nt][0] = (c0     <= r0    ) ? acc[nt][0] * 0.125f : -1e30f;
        acc[nt][1] = (c0 + 1 <= r0    ) ? acc[nt][1] * 0.125f : -1e30f;
        acc[nt][2] = (c0     <= r0 + 8) ? acc[nt][2] * 0.125f : -1e30f;
        acc[nt][3] = (c0 + 1 <= r0 + 8) ? acc[nt][3] * 0.125f : -1e30f;
        mx0 = fmaxf(mx0, fmaxf(acc[nt][0], acc[nt][1]));
        mx1 = fmaxf(mx1, fmaxf(acc[nt][2], acc[nt][3]));
    }
    mx0 = fmaxf(mx0, __shfl_xor_sync(0xffffffffu, mx0, 1));
    mx0 = fmaxf(mx0, __shfl_xor_sync(0xffffffffu, mx0, 2));
    mx1 = fmaxf(mx1, __shfl_xor_sync(0xffffffffu, mx1, 1));
    mx1 = fmaxf(mx1, __shfl_xor_sync(0xffffffffu, mx1, 2));

    float l0 = 0.f, l1 = 0.f;
    #pragma unroll
    for (int nt = 0; nt < 16; ++nt) {
        acc[nt][0] = __expf(acc[nt][0] - mx0);
        acc[nt][1] = __expf(acc[nt][1] - mx0);
        acc[nt][2] = __expf(acc[nt][2] - mx1);
        acc[nt][3] = __expf(acc[nt][3] - mx1);
        l0 += acc[nt][0] + acc[nt][1];
        l1 += acc[nt][2] + acc[nt][3];
    }
    l0 += __shfl_xor_sync(0xffffffffu, l0, 1);
    l0 += __shfl_xor_sync(0xffffffffu, l0, 2);
    l1 += __shfl_xor_sync(0xffffffffu, l1, 1);
    l1 += __shfl_xor_sync(0xffffffffu, l1, 2);
    const float inv0 = 1.f / l0, inv1 = 1.f / l1;

    {
        const uint32_t p0 = sb + AT_P + r0 * 256;
        const uint32_t p1 = sb + AT_P + (r0 + 8) * 256;
        const int cb = (lane & 3) * 4;
        const int x0 = (r0 & 7) * 16, x1 = ((r0 + 8) & 7) * 16;
        #pragma unroll
        for (int nt = 0; nt < 16; ++nt) {
            __half2 h0 = __floats2half2_rn(acc[nt][0], acc[nt][1]);
            __half2 h1 = __floats2half2_rn(acc[nt][2], acc[nt][3]);
            *(__half2*)(smf + (p0 - sb) + ((nt * 16 + cb) ^ x0)) = h0;
            *(__half2*)(smf + (p1 - sb) + ((nt * 16 + cb) ^ x1)) = h1;
        }
    }
    __syncwarp();   // warp reads only its own P rows below

    float ao[8][4];
    #pragma unroll
    for (int i = 0; i < 8; ++i)
        #pragma unroll
        for (int c = 0; c < 4; ++c) ao[i][c] = 0.f;

    const int ks_max = w + 1;
    #pragma unroll 1
    for (int ks = 0; ks < ks_max; ++ks) {
        uint32_t af[4];
        LDMATRIX_X4(af[0], af[1], af[2], af[3],
                    sb + AT_P + arow * 256 + ((ks * 32 + akb) ^ xa));
        #pragma unroll
        for (int np = 0; np < 4; ++np) {
            const int srow = ks * 16 + brow8;
            uint32_t bf[4];
            LDMATRIX_X4_T(bf[0], bf[1], bf[2], bf[3],
                          sb + AT_V + srow * 128 + ((np * 32 + bkb) ^ ((srow & 7) * 16)));
            MMA_F16(ao[2*np],   af, bf[0], bf[1]);
            MMA_F16(ao[2*np+1], af, bf[2], bf[3]);
        }
    }

    {
        const size_t row0 = ((size_t)(b * TT + r0) * NN + n) * DD + head * DH
                          + (lane & 3) * 2;
        const size_t row1 = ((size_t)(b * TT + r0 + 8) * NN + n) * DD + head * DH
                          + (lane & 3) * 2;
        #pragma unroll
        for (int nt = 0; nt < 8; ++nt) {
            *(__half2*)(g_attn + row0 + nt * 8) =
                __floats2half2_rn(ao[nt][0] * inv0, ao[nt][1] * inv0);
            *(__half2*)(g_attn + row1 + nt * 8) =
                __floats2half2_rn(ao[nt][2] * inv1, ao[nt][3] * inv1);
        }
    }
}

// ---------------------------------------------------------------------------
extern "C" void kernel_launch(void* const* d_in, const int* in_sizes, int n_in,
                              void* d_out, int out_size)
{
    const float* X   = (const float*)d_in[0];
    const float* STE = (const float*)d_in[1];
    const float* Wq  = (const float*)d_in[2];
    const float* bq  = (const float*)d_in[3];
    const float* Wk  = (const float*)d_in[4];
    const float* bk  = (const float*)d_in[5];
    const float* Wv  = (const float*)d_in[6];
    const float* bv  = (const float*)d_in[7];
    const float* Wo  = (const float*)d_in[8];
    const float* bo  = (const float*)d_in[9];
    float* out = (float*)d_out;

    cudaFuncSetAttribute(gemm3<true>,  cudaFuncAttributeMaxDynamicSharedMemorySize, SMEM_REQ);
    cudaFuncSetAttribute(gemm3<false>, cudaFuncAttributeMaxDynamicSharedMemorySize, SMEM_REQ);
    cudaFuncSetAttribute(attn_tc,      cudaFuncAttributeMaxDynamicSharedMemorySize, AT_SMEM);

    // Merged prepass: activations + all weights in one launch
    prep_all<<<MTOT + 1536 + 512, 384>>>(X, STE, Wq, Wk, Wv, Wo);

    // QKV: grid (z*4+ntile, mtile) — z-adjacent CTAs reuse the A m-tile in L2
    gemm3<true><<<dim3(12, 512), 128, SMEM_REQ>>>(bq, bk, bv, nullptr);
    attn_tc<<<dim3(KH, NN, BB), 256, AT_SMEM>>>();
    gemm3<false><<<dim3(4, 512), 128, SMEM_REQ>>>(bo, bo, bo, out);
}